// round 7
// baseline (speedup 1.0000x reference)
#include <cuda_runtime.h>

#define BB   2048
#define HIST 50
#define DIM  64
#define SS   32

__device__ float g_scores[BB];

// ---------------------------------------------------------------------------
// K_fused: one block per batch item. 256 threads. Static smem ~41.8 KB.
//   s_x   : x-tiles (self||agg) per node; h1[g] overwrites s_x[g][0..15]
//   s_scr : user-emb partials (early), MLP partials (late) — disjoint lifetimes
// ---------------------------------------------------------------------------
__global__ void __launch_bounds__(256, 4) k_fused(
    const int*   __restrict__ user_inputs,
    const int*   __restrict__ item_inputs,
    const int*   __restrict__ n_idxs,
    const float* __restrict__ emb,
    const int*   __restrict__ adj_item,
    const float* __restrict__ adj_adam,
    const float* __restrict__ pool_w,   // [128][64]
    const float* __restrict__ pool_b,   // [64]
    const float* __restrict__ fc1_w,    // [128][32]
    const float* __restrict__ fc1_b,    // [32]
    const float* __restrict__ fc2_w,    // [32]
    const float* __restrict__ fc2_b)    // [1]
{
    __shared__ float  s_w1[SS][SS];     // 4 KB
    __shared__ int    s_nbr[SS][SS];    // 4 KB
    __shared__ int    s_e[SS];
    __shared__ float  s_w0[SS];
    __shared__ float  s_red[8];
    __shared__ float  s_maxn;
    __shared__ float4 s_x[SS][32];      // 16 KB
    __shared__ float4 s_scr[1024];      // 16 KB multi-use scratch
    __shared__ float4 s_p1x[32];        // pool1 input [self||agg]
    __shared__ float4 s_p2x[32];        // pool2 input [h0||agg2]
    __shared__ float4 s_fcx[32];        // fc input [user||item]

    int b = blockIdx.x, t = threadIdx.x;
    int warp = t >> 5, lane = t & 31;
    int item = __ldg(item_inputs + b);
    const float4* emb4 = (const float4*)emb;

    // ---- Phase 1a: block-local max(n_idxs) ----
    {
        int m = 0;
        for (int p = t; p < BB; p += 256) m = max(m, __ldg(n_idxs + p));
        #pragma unroll
        for (int o = 16; o > 0; o >>= 1) m = max(m, __shfl_xor_sync(0xffffffffu, m, o));
        if (lane == 0) s_red[warp] = (float)m;
    }

    // ---- Phase 1b: 32 level-1 softmaxes (4 per warp) ----
    #pragma unroll
    for (int q = 0; q < 4; q++) {
        int g = warp * 4 + q;
        int e = __ldg(adj_item + (size_t)item * SS + g);
        float a  = __ldg(adj_adam + (size_t)e * SS + lane);
        int  nbr = __ldg(adj_item + (size_t)e * SS + lane);
        float m = a;
        #pragma unroll
        for (int o = 16; o > 0; o >>= 1) m = fmaxf(m, __shfl_xor_sync(0xffffffffu, m, o));
        float ex = expf(a - m);
        float ssum = ex;
        #pragma unroll
        for (int o = 16; o > 0; o >>= 1) ssum += __shfl_xor_sync(0xffffffffu, ssum, o);
        s_w1[g][lane]  = ex / ssum;
        s_nbr[g][lane] = nbr;
        if (lane == 0) s_e[g] = e;
    }
    // ---- Phase 1c: level-0 softmax (warp 0) ----
    if (warp == 0) {
        float a = __ldg(adj_adam + (size_t)item * SS + lane);
        float m = a;
        #pragma unroll
        for (int o = 16; o > 0; o >>= 1) m = fmaxf(m, __shfl_xor_sync(0xffffffffu, m, o));
        float ex = expf(a - m);
        float ssum = ex;
        #pragma unroll
        for (int o = 16; o > 0; o >>= 1) ssum += __shfl_xor_sync(0xffffffffu, ssum, o);
        s_w0[lane] = ex / ssum;
    }
    __syncthreads();
    if (t == 0) {
        float mm = s_red[0];
        #pragma unroll
        for (int q = 1; q < 8; q++) mm = fmaxf(mm, s_red[q]);
        s_maxn = mm;
    }

    int i = t & 15, half = t >> 4;

    // ---- Phase 2a: user-emb gather partials -> s_scr[half*16+i] ----
    {
        int n = __ldg(n_idxs + b);
        const int* row = user_inputs + b * HIST;
        float4 ua = make_float4(0.f, 0.f, 0.f, 0.f);
        for (int p = half; p < n; p += 16) {
            int idx = __ldg(row + p);
            float4 v = __ldg(emb4 + (size_t)idx * 16 + i);
            ua.x += v.x; ua.y += v.y; ua.z += v.z; ua.w += v.w;
        }
        s_scr[half * 16 + i] = ua;
    }

    // ---- Phase 2b: node gathers, 2 nodes per thread ----
    #pragma unroll
    for (int rep = 0; rep < 2; rep++) {
        int g = half + rep * 16;
        float4 self4 = __ldg(emb4 + (size_t)s_e[g] * 16 + i);
        float4 agg = make_float4(0.f, 0.f, 0.f, 0.f);
        #pragma unroll 8
        for (int j = 0; j < SS; j++) {
            float  wj = s_w1[g][j];
            float4 v  = __ldg(emb4 + (size_t)s_nbr[g][j] * 16 + i);
            agg.x += wj * v.x; agg.y += wj * v.y; agg.z += wj * v.z; agg.w += wj * v.w;
        }
        s_x[g][i]      = self4;
        s_x[g][16 + i] = agg;
    }
    __syncthreads();

    // ---- Phase 3: user reduce (t<16), pool1 agg (16..31), pool1 self (32..47) ----
    if (t < 16) {
        float4 s = s_scr[t];
        #pragma unroll
        for (int h = 1; h < 16; h++) {
            float4 v = s_scr[h * 16 + t];
            s.x += v.x; s.y += v.y; s.z += v.z; s.w += v.w;
        }
        float inv = 1.f / s_maxn;
        s.x *= inv; s.y *= inv; s.z *= inv; s.w *= inv;
        s_fcx[t] = s;
    } else if (t < 32) {
        int ii = t - 16;
        float4 s = make_float4(0.f, 0.f, 0.f, 0.f);
        #pragma unroll 8
        for (int g = 0; g < SS; g++) {
            float w = s_w0[g];
            float4 v = s_x[g][ii];
            s.x += w * v.x; s.y += w * v.y; s.z += w * v.z; s.w += w * v.w;
        }
        s_p1x[16 + ii] = s;
    } else if (t < 48) {
        int ii = t - 32;
        s_p1x[ii] = __ldg(emb4 + (size_t)item * 16 + ii);
    }
    __syncthreads();      // s_scr reads done before MLP partials overwrite it

    // ---- Phase 4: big MLP, 4 octets. i = out quad, half = k-slice of 16.
    //      Pair-reduce halves (half, half^1) via shfl_xor(16) -> s_scr[8][8][16]
    const float4* pw4 = (const float4*)pool_w;
    float4 bias = __ldg(((const float4*)pool_b) + i);
    #pragma unroll
    for (int grp = 0; grp < 4; grp++) {
        float4 acc[8];
        #pragma unroll
        for (int n = 0; n < 8; n++) acc[n] = make_float4(0.f, 0.f, 0.f, 0.f);
        #pragma unroll
        for (int kk = 0; kk < 2; kk++) {
            int k4 = half * 2 + kk;
            float4 wA = __ldg(pw4 + (size_t)(k4 * 4 + 0) * 16 + i);
            float4 wB = __ldg(pw4 + (size_t)(k4 * 4 + 1) * 16 + i);
            float4 wC = __ldg(pw4 + (size_t)(k4 * 4 + 2) * 16 + i);
            float4 wD = __ldg(pw4 + (size_t)(k4 * 4 + 3) * 16 + i);
            #pragma unroll
            for (int n = 0; n < 8; n++) {
                float4 xv = s_x[grp * 8 + n][k4];
                acc[n].x += xv.x*wA.x + xv.y*wB.x + xv.z*wC.x + xv.w*wD.x;
                acc[n].y += xv.x*wA.y + xv.y*wB.y + xv.z*wC.y + xv.w*wD.y;
                acc[n].z += xv.x*wA.z + xv.y*wB.z + xv.z*wC.z + xv.w*wD.z;
                acc[n].w += xv.x*wA.w + xv.y*wB.w + xv.z*wC.w + xv.w*wD.w;
            }
        }
        // pair-reduce across (half, half^1): lanes l <-> l^16 of same warp
        #pragma unroll
        for (int n = 0; n < 8; n++) {
            acc[n].x += __shfl_xor_sync(0xffffffffu, acc[n].x, 16);
            acc[n].y += __shfl_xor_sync(0xffffffffu, acc[n].y, 16);
            acc[n].z += __shfl_xor_sync(0xffffffffu, acc[n].z, 16);
            acc[n].w += __shfl_xor_sync(0xffffffffu, acc[n].w, 16);
        }
        if ((half & 1) == 0) {
            int hp = half >> 1;
            #pragma unroll
            for (int n = 0; n < 8; n++) s_scr[hp * 128 + n * 16 + i] = acc[n];
        }
        __syncthreads();
        if (t < 128) {     // reduce 8 half-pairs, bias+relu, h1 -> s_x[node][0..15]
            int n = t >> 4, ii = t & 15;
            float4 r = s_scr[n * 16 + ii];
            #pragma unroll
            for (int h = 1; h < 8; h++) {
                float4 p = s_scr[h * 128 + n * 16 + ii];
                r.x += p.x; r.y += p.y; r.z += p.z; r.w += p.w;
            }
            r.x = fmaxf(r.x + bias.x, 0.f); r.y = fmaxf(r.y + bias.y, 0.f);
            r.z = fmaxf(r.z + bias.z, 0.f); r.w = fmaxf(r.w + bias.w, 0.f);
            s_x[grp * 8 + n][ii] = r;
        }
        __syncthreads();
    }

    // ---- Phase 5: pool2 agg = sum_g w0[g] * h1_g (h1 lives in s_x[g][0..15]) ----
    if (t < 16) {
        float4 s = make_float4(0.f, 0.f, 0.f, 0.f);
        #pragma unroll 8
        for (int g = 0; g < SS; g++) {
            float w = s_w0[g];
            float4 v = s_x[g][t];
            s.x += w * v.x; s.y += w * v.y; s.z += w * v.z; s.w += w * v.w;
        }
        s_p2x[16 + t] = s;
    }

    // ---- Phase 6: pool1 MLP -> h0 (k-split-16, partials in s_scr[0..255]) ----
    {
        float4 a0 = make_float4(0.f, 0.f, 0.f, 0.f);
        #pragma unroll
        for (int kk = 0; kk < 2; kk++) {
            int k4 = half * 2 + kk;
            float4 wA = __ldg(pw4 + (size_t)(k4 * 4 + 0) * 16 + i);
            float4 wB = __ldg(pw4 + (size_t)(k4 * 4 + 1) * 16 + i);
            float4 wC = __ldg(pw4 + (size_t)(k4 * 4 + 2) * 16 + i);
            float4 wD = __ldg(pw4 + (size_t)(k4 * 4 + 3) * 16 + i);
            float4 xv = s_p1x[k4];
            a0.x += xv.x*wA.x + xv.y*wB.x + xv.z*wC.x + xv.w*wD.x;
            a0.y += xv.x*wA.y + xv.y*wB.y + xv.z*wC.y + xv.w*wD.y;
            a0.z += xv.x*wA.z + xv.y*wB.z + xv.z*wC.z + xv.w*wD.z;
            a0.w += xv.x*wA.w + xv.y*wB.w + xv.z*wC.w + xv.w*wD.w;
        }
        s_scr[half * 16 + i] = a0;
    }
    __syncthreads();
    if (t < 16) {
        float4 r = s_scr[t];
        #pragma unroll
        for (int h = 1; h < 16; h++) {
            float4 p = s_scr[h * 16 + t];
            r.x += p.x; r.y += p.y; r.z += p.z; r.w += p.w;
        }
        float4 bs = __ldg(((const float4*)pool_b) + t);
        r.x = fmaxf(r.x + bs.x, 0.f); r.y = fmaxf(r.y + bs.y, 0.f);
        r.z = fmaxf(r.z + bs.z, 0.f); r.w = fmaxf(r.w + bs.w, 0.f);
        s_p2x[t] = r;
    }
    __syncthreads();

    // ---- Phase 7: pool2 MLP -> item emb ----
    {
        float4 a0 = make_float4(0.f, 0.f, 0.f, 0.f);
        #pragma unroll
        for (int kk = 0; kk < 2; kk++) {
            int k4 = half * 2 + kk;
            float4 wA = __ldg(pw4 + (size_t)(k4 * 4 + 0) * 16 + i);
            float4 wB = __ldg(pw4 + (size_t)(k4 * 4 + 1) * 16 + i);
            float4 wC = __ldg(pw4 + (size_t)(k4 * 4 + 2) * 16 + i);
            float4 wD = __ldg(pw4 + (size_t)(k4 * 4 + 3) * 16 + i);
            float4 xv = s_p2x[k4];
            a0.x += xv.x*wA.x + xv.y*wB.x + xv.z*wC.x + xv.w*wD.x;
            a0.y += xv.x*wA.y + xv.y*wB.y + xv.z*wC.y + xv.w*wD.y;
            a0.z += xv.x*wA.z + xv.y*wB.z + xv.z*wC.z + xv.w*wD.z;
            a0.w += xv.x*wA.w + xv.y*wB.w + xv.z*wC.w + xv.w*wD.w;
        }
        s_scr[half * 16 + i] = a0;
    }
    __syncthreads();
    if (t < 16) {
        float4 r = s_scr[t];
        #pragma unroll
        for (int h = 1; h < 16; h++) {
            float4 p = s_scr[h * 16 + t];
            r.x += p.x; r.y += p.y; r.z += p.z; r.w += p.w;
        }
        float4 bs = __ldg(((const float4*)pool_b) + t);
        r.x = fmaxf(r.x + bs.x, 0.f); r.y = fmaxf(r.y + bs.y, 0.f);
        r.z = fmaxf(r.z + bs.z, 0.f); r.w = fmaxf(r.w + bs.w, 0.f);
        s_fcx[16 + t] = r;
    }
    __syncthreads();

    // ---- Phase 8: fc1 (128->32) k-split-8, then fc2 ----
    {
        int o = t & 31, h8 = t >> 5;
        const float* fcx = (const float*)s_fcx;
        float a0 = 0.f;
        #pragma unroll
        for (int kk = 0; kk < 16; kk++) {
            int k = h8 * 16 + kk;
            a0 += fcx[k] * __ldg(fc1_w + k * 32 + o);
        }
        ((float*)s_scr)[h8 * 32 + o] = a0;
    }
    __syncthreads();
    if (t < 32) {
        const float* pf = (const float*)s_scr;
        float y = __ldg(fc1_b + t);
        #pragma unroll
        for (int h = 0; h < 8; h++) y += pf[h * 32 + t];
        y = fmaxf(y, 0.f);
        float p = y * __ldg(fc2_w + t);
        #pragma unroll
        for (int o = 16; o > 0; o >>= 1) p += __shfl_xor_sync(0xffffffffu, p, o);
        if (t == 0) g_scores[b] = p + __ldg(fc2_b);
    }
}

// ---------------------------------------------------------------------------
// K_softmax: batch softmax, shuffle-based
// ---------------------------------------------------------------------------
__global__ void k_softmax(float* __restrict__ out) {
    __shared__ float rmax[32], rsum[32];
    int t = threadIdx.x, lane = t & 31, w = t >> 5;
    float a0 = g_scores[t], a1 = g_scores[t + 1024];
    float m = fmaxf(a0, a1);
    #pragma unroll
    for (int o = 16; o > 0; o >>= 1) m = fmaxf(m, __shfl_xor_sync(0xffffffffu, m, o));
    if (lane == 0) rmax[w] = m;
    __syncthreads();
    if (t < 32) {
        float mm = rmax[t];
        #pragma unroll
        for (int o = 16; o > 0; o >>= 1) mm = fmaxf(mm, __shfl_xor_sync(0xffffffffu, mm, o));
        rmax[t] = mm;
    }
    __syncthreads();
    float gm = rmax[0];
    float e0 = expf(a0 - gm), e1 = expf(a1 - gm);
    float s = e0 + e1;
    #pragma unroll
    for (int o = 16; o > 0; o >>= 1) s += __shfl_xor_sync(0xffffffffu, s, o);
    if (lane == 0) rsum[w] = s;
    __syncthreads();
    if (t < 32) {
        float ss = rsum[t];
        #pragma unroll
        for (int o = 16; o > 0; o >>= 1) ss += __shfl_xor_sync(0xffffffffu, ss, o);
        rsum[t] = ss;
    }
    __syncthreads();
    float inv = 1.f / rsum[0];
    out[t]        = e0 * inv;
    out[t + 1024] = e1 * inv;
}

// ---------------------------------------------------------------------------
extern "C" void kernel_launch(void* const* d_in, const int* in_sizes, int n_in,
                              void* d_out, int out_size) {
    const int*   user_inputs = (const int*)  d_in[0];
    const int*   item_inputs = (const int*)  d_in[1];
    const int*   n_idxs      = (const int*)  d_in[2];
    const float* emb         = (const float*)d_in[3];
    const int*   adj_item    = (const int*)  d_in[4];
    const float* adj_adam    = (const float*)d_in[5];
    const float* pool_w      = (const float*)d_in[6];
    const float* pool_b      = (const float*)d_in[7];
    const float* fc1_w       = (const float*)d_in[8];
    const float* fc1_b       = (const float*)d_in[9];
    const float* fc2_w       = (const float*)d_in[10];
    const float* fc2_b       = (const float*)d_in[11];
    float* out = (float*)d_out;

    k_fused<<<BB, 256>>>(user_inputs, item_inputs, n_idxs, emb, adj_item, adj_adam,
                         pool_w, pool_b, fc1_w, fc1_b, fc2_w, fc2_b);
    k_softmax<<<1, 1024>>>(out);
}